// round 7
// baseline (speedup 1.0000x reference)
#include <cuda_runtime.h>
#include <cuda_bf16.h>
#include <cstdint>

#define N_NODES 1000
#define HIDDEN  256
#define IN_DIM  128
#define N_EDGES 64000

// Scratch (device globals: no allocation allowed)
__device__ float g_C[N_NODES * HIDDEN];    // A - B + b1   (per node)
__device__ float g_B[N_NODES * HIDDEN];    // B = X @ W1b^T (per node)
__device__ float g_H[N_NODES * HIDDEN];    // node features between layers
__device__ __nv_bfloat16 g_Whi[HIDDEN * HIDDEN];  // W2 hi (bf16, [n][k] k-major)
__device__ __nv_bfloat16 g_Wlo[HIDDEN * HIDDEN];  // W2 lo residual
__device__ int   g_src[N_EDGES];
__device__ int   g_dst[N_EDGES];
__device__ int   g_src2[N_EDGES];   // dst-sorted
__device__ int   g_dst2[N_EDGES];
__device__ int   g_cnt[N_NODES];
__device__ int   g_ofs[N_NODES];
__device__ int   g_is64;

// ---------------------------------------------------------------------------
__device__ __forceinline__ uint32_t smem_u32(const void* p) {
    uint32_t a;
    asm("{ .reg .u64 t; cvta.to.shared.u64 t, %1; cvt.u32.u64 %0, t; }"
        : "=r"(a) : "l"(p));
    return a;
}
__device__ __forceinline__ void ldmatrix_x4(uint32_t* r, uint32_t addr) {
    asm volatile(
        "ldmatrix.sync.aligned.m8n8.x4.shared.b16 {%0, %1, %2, %3}, [%4];"
        : "=r"(r[0]), "=r"(r[1]), "=r"(r[2]), "=r"(r[3]) : "r"(addr));
}
__device__ __forceinline__ void mma_bf16(float* d, const uint32_t* a,
                                         const uint32_t* b) {
    asm volatile(
        "mma.sync.aligned.m16n8k16.row.col.f32.bf16.bf16.f32 "
        "{%0, %1, %2, %3}, {%4, %5, %6, %7}, {%8, %9}, {%0, %1, %2, %3};"
        : "+f"(d[0]), "+f"(d[1]), "+f"(d[2]), "+f"(d[3])
        : "r"(a[0]), "r"(a[1]), "r"(a[2]), "r"(a[3]), "r"(b[0]), "r"(b[1]));
}
__device__ __forceinline__ void cp_async16(uint32_t saddr, const void* gaddr) {
    asm volatile("cp.async.ca.shared.global [%0], [%1], 16;"
                 :: "r"(saddr), "l"(gaddr));
}
__device__ __forceinline__ void cp_commit() {
    asm volatile("cp.async.commit_group;");
}
__device__ __forceinline__ void cp_wait0() {
    asm volatile("cp.async.wait_group 0;");
}

// ---------------------------------------------------------------------------
// Edge-index dtype detection + int32 materialization (clamped)
__global__ void detect_idx(const unsigned int* __restrict__ w) {
    if (threadIdx.x == 0 && blockIdx.x == 0) {
        int is64 = 1;
        for (int i = 0; i < 128; i++)
            if (w[2 * i + 1] != 0u) { is64 = 0; break; }
        g_is64 = is64;
    }
}
__global__ void convert_idx(const int* __restrict__ raw) {
    int e = blockIdx.x * blockDim.x + threadIdx.x;
    if (e >= N_EDGES) return;
    int s, d;
    if (g_is64) { s = raw[2 * e]; d = raw[2 * (N_EDGES + e)]; }
    else        { s = raw[e];     d = raw[N_EDGES + e]; }
    g_src[e] = min(max(s, 0), N_NODES - 1);
    g_dst[e] = min(max(d, 0), N_NODES - 1);
}

// ---------------------------------------------------------------------------
// Counting sort by dst (runs once per launch; output order within a dst
// segment is nondeterministic but consumed only by max-reduction).
__global__ void zero_cnt() {
    int i = blockIdx.x * blockDim.x + threadIdx.x;
    if (i < N_NODES) g_cnt[i] = 0;
}
__global__ void hist_kernel() {
    int e = blockIdx.x * blockDim.x + threadIdx.x;
    if (e < N_EDGES) atomicAdd(&g_cnt[g_dst[e]], 1);
}
__global__ __launch_bounds__(1024) void scan_kernel() {
    __shared__ int s[1024];
    int t = threadIdx.x;
    int c = (t < N_NODES) ? g_cnt[t] : 0;
    s[t] = c;
    __syncthreads();
#pragma unroll
    for (int off = 1; off < 1024; off <<= 1) {
        int v = (t >= off) ? s[t - off] : 0;
        __syncthreads();
        s[t] += v;
        __syncthreads();
    }
    if (t < N_NODES) g_ofs[t] = s[t] - c;  // exclusive prefix
}
__global__ void perm_kernel() {
    int e = blockIdx.x * blockDim.x + threadIdx.x;
    if (e >= N_EDGES) return;
    int d = g_dst[e];
    int p = atomicAdd(&g_ofs[d], 1);
    g_src2[p] = g_src[e];
    g_dst2[p] = d;
}

// ---------------------------------------------------------------------------
// zero-fill (p == nullptr -> zero g_H)
__global__ void zero_kernel(float4* __restrict__ p, int n4) {
    float4* dst = p ? p : (float4*)g_H;
    int i = blockIdx.x * blockDim.x + threadIdx.x;
    if (i < n4) dst[i] = make_float4(0.f, 0.f, 0.f, 0.f);
}

// ---------------------------------------------------------------------------
// W2 fp32 -> (hi, lo) bf16 pair
__global__ void convert_w2(const float* __restrict__ W2) {
    int i = blockIdx.x * blockDim.x + threadIdx.x;
    if (i >= HIDDEN * HIDDEN) return;
    float w = W2[i];
    __nv_bfloat16 hi = __float2bfloat16(w);
    __nv_bfloat16 lo = __float2bfloat16(w - __bfloat162float(hi));
    g_Whi[i] = hi;
    g_Wlo[i] = lo;
}

// ---------------------------------------------------------------------------
// Node GEMM: C = A - B + b1, B = H @ W1b^T  (fp32, tiny: 1000x256)
template <int DIN>
__global__ __launch_bounds__(256) void node_gemm(
    const float* __restrict__ Hin, const float* __restrict__ W1,
    const float* __restrict__ b1)
{
    const float* H = Hin ? Hin : g_H;
    __shared__ float Hs[16][DIN];
    const int tid = threadIdx.x;
    const int n_base = blockIdx.x * 16;

    const int nvec = 16 * DIN / 4;
    for (int i = tid; i < nvec; i += 256) {
        int row = i / (DIN / 4);
        int c4 = i % (DIN / 4);
        int n = n_base + row;
        float4 v = make_float4(0.f, 0.f, 0.f, 0.f);
        if (n < N_NODES) v = ((const float4*)(H + (size_t)n * DIN))[c4];
        ((float4*)&Hs[row][0])[c4] = v;
    }
    __syncthreads();

    const int o = blockIdx.y * 128 + (tid & 127);
    const int ng = tid >> 7;

    float accA[8], accB[8];
#pragma unroll
    for (int j = 0; j < 8; j++) { accA[j] = 0.f; accB[j] = 0.f; }

    const float4* wA4 = (const float4*)(W1 + (size_t)o * 2 * DIN);
    const float4* wB4 = (const float4*)(W1 + (size_t)o * 2 * DIN + DIN);

    for (int k4 = 0; k4 < DIN / 4; k4++) {
        float4 wa = wA4[k4];
        float4 wb = wB4[k4];
        int kk = k4 * 4;
#pragma unroll
        for (int j = 0; j < 8; j++) {
            float h0 = Hs[ng * 8 + j][kk + 0];
            float h1 = Hs[ng * 8 + j][kk + 1];
            float h2 = Hs[ng * 8 + j][kk + 2];
            float h3 = Hs[ng * 8 + j][kk + 3];
            accA[j] += h0 * wa.x + h1 * wa.y + h2 * wa.z + h3 * wa.w;
            accB[j] += h0 * wb.x + h1 * wb.y + h2 * wb.z + h3 * wb.w;
        }
    }

    float bb = b1[o];
#pragma unroll
    for (int j = 0; j < 8; j++) {
        int n = n_base + ng * 8 + j;
        if (n < N_NODES) {
            g_B[n * HIDDEN + o] = accB[j];
            g_C[n * HIDDEN + o] = accA[j] - accB[j] + bb;
        }
    }
}

// ---------------------------------------------------------------------------
// HMMA fused edge kernel: TM=128 sorted edges x TN=256 cols, 512 threads.
// Double-buffered K chunks of 32; W via cp.async; Z gather pipelined.
// Epilogue: smem stage + segmented max-scan (sorted dst) -> few atomics.

#define TM 128
#define TN 256
#define TK 32
#define SK 40   // padded bf16 k-stride
#define SKO 132 // padded fp32 stage stride (conflict-free)

#define A_STAGE (TM * SK * 2)
#define B_STAGE (TN * SK * 2)
#define OFF_AHI 0
#define OFF_ALO (2 * A_STAGE)
#define OFF_BHI (4 * A_STAGE)
#define OFF_BLO (4 * A_STAGE + 2 * B_STAGE)
#define OFF_DST (4 * A_STAGE + 4 * B_STAGE)
#define OFF_SRC (OFF_DST + 512)
#define OFF_B2  (OFF_SRC + 512)
#define SM_TOTAL (OFF_B2 + 1024)

__global__ __launch_bounds__(512, 1) void edge_hmma_kernel(
    const float* __restrict__ b2, float* __restrict__ outp)
{
    extern __shared__ char smem[];
    float* out = outp ? outp : g_H;
    const uint32_t sb = smem_u32(smem);
    const int tid = threadIdx.x;
    const int wid = tid >> 5;
    const int lane = tid & 31;
    const int e0 = blockIdx.x * TM;

    int* dstS = (int*)(smem + OFF_DST);
    int* srcS = (int*)(smem + OFF_SRC);
    float* b2s = (float*)(smem + OFF_B2);

    if (tid < TM) {
        srcS[tid] = g_src2[e0 + tid];
        dstS[tid] = g_dst2[e0 + tid];
    }
    if (tid < 256) b2s[tid] = b2[tid];
    __syncthreads();

    const int wm = (wid >> 2) * 32;
    const int wn = (wid & 3) * 64;

    float acc[2][8][4];
#pragma unroll
    for (int i = 0; i < 2; i++)
#pragma unroll
        for (int j = 0; j < 8; j++)
#pragma unroll
            for (int r = 0; r < 4; r++) acc[i][j][r] = 0.f;

    const int a_row = lane & 15;
    const int a_kof = (lane >> 4) << 3;
    const int b_row = ((lane >> 4) << 3) + (lane & 7);
    const int b_kof = ((lane >> 3) & 1) << 3;

    auto issue_W = [&](int buf, int kt) {
#pragma unroll
        for (int i = 0; i < 2; i++) {
            int id = tid + i * 512;
            int row = id >> 2;
            int k8 = (id & 3) * 8;
            uint32_t so = (uint32_t)(row * SK + k8) * 2;
            cp_async16(sb + OFF_BHI + buf * B_STAGE + so,
                       &g_Whi[row * HIDDEN + kt + k8]);
            cp_async16(sb + OFF_BLO + buf * B_STAGE + so,
                       &g_Wlo[row * HIDDEN + kt + k8]);
        }
        cp_commit();
    };
    auto ldg_Z = [&](int h, int kt, float4& cz, float4& bz) {
        int id = tid + h * 512;
        int row = id >> 3;
        int k4 = (id & 7) * 4;
        cz = *(const float4*)&g_C[dstS[row] * HIDDEN + kt + k4];
        bz = *(const float4*)&g_B[srcS[row] * HIDDEN + kt + k4];
    };
    auto sts_Z = [&](int h, int buf, const float4& cz, const float4& bz) {
        int id = tid + h * 512;
        int row = id >> 3;
        int k4 = (id & 7) * 4;
        float z0 = fmaxf(cz.x + bz.x, 0.f);
        float z1 = fmaxf(cz.y + bz.y, 0.f);
        float z2 = fmaxf(cz.z + bz.z, 0.f);
        float z3 = fmaxf(cz.w + bz.w, 0.f);
        __nv_bfloat16 h0 = __float2bfloat16(z0), h1 = __float2bfloat16(z1);
        __nv_bfloat16 h2 = __float2bfloat16(z2), h3 = __float2bfloat16(z3);
        __nv_bfloat16 l0 = __float2bfloat16(z0 - __bfloat162float(h0));
        __nv_bfloat16 l1 = __float2bfloat16(z1 - __bfloat162float(h1));
        __nv_bfloat16 l2 = __float2bfloat16(z2 - __bfloat162float(h2));
        __nv_bfloat16 l3 = __float2bfloat16(z3 - __bfloat162float(h3));
        uint32_t hp0 = ((uint32_t)__bfloat16_as_ushort(h1) << 16) | __bfloat16_as_ushort(h0);
        uint32_t hp1 = ((uint32_t)__bfloat16_as_ushort(h3) << 16) | __bfloat16_as_ushort(h2);
        uint32_t lp0 = ((uint32_t)__bfloat16_as_ushort(l1) << 16) | __bfloat16_as_ushort(l0);
        uint32_t lp1 = ((uint32_t)__bfloat16_as_ushort(l3) << 16) | __bfloat16_as_ushort(l2);
        uint32_t eo = (uint32_t)(row * SK + k4) * 2;
        *(uint2*)(smem + OFF_AHI + buf * A_STAGE + eo) = make_uint2(hp0, hp1);
        *(uint2*)(smem + OFF_ALO + buf * A_STAGE + eo) = make_uint2(lp0, lp1);
    };
    auto mma_ks = [&](int buf, int ks) {
        uint32_t ahi[2][4], alo[2][4];
#pragma unroll
        for (int mt = 0; mt < 2; mt++) {
            uint32_t ao = (uint32_t)((wm + mt * 16 + a_row) * SK + ks + a_kof) * 2;
            ldmatrix_x4(ahi[mt], sb + OFF_AHI + buf * A_STAGE + ao);
            ldmatrix_x4(alo[mt], sb + OFF_ALO + buf * A_STAGE + ao);
        }
#pragma unroll
        for (int nt = 0; nt < 4; nt++) {
            uint32_t bhi[4], blo[4];
            uint32_t bo = (uint32_t)((wn + nt * 16 + b_row) * SK + ks + b_kof) * 2;
            ldmatrix_x4(bhi, sb + OFF_BHI + buf * B_STAGE + bo);
            ldmatrix_x4(blo, sb + OFF_BLO + buf * B_STAGE + bo);
#pragma unroll
            for (int mt = 0; mt < 2; mt++) {
                mma_bf16(acc[mt][nt * 2 + 0], ahi[mt], &bhi[0]);
                mma_bf16(acc[mt][nt * 2 + 1], ahi[mt], &bhi[2]);
                mma_bf16(acc[mt][nt * 2 + 0], ahi[mt], &blo[0]);
                mma_bf16(acc[mt][nt * 2 + 1], ahi[mt], &blo[2]);
                mma_bf16(acc[mt][nt * 2 + 0], alo[mt], &bhi[0]);
                mma_bf16(acc[mt][nt * 2 + 1], alo[mt], &bhi[2]);
            }
        }
    };

    // prologue
    {
        issue_W(0, 0);
        float4 cz0, bz0, cz1, bz1;
        ldg_Z(0, 0, cz0, bz0);
        ldg_Z(1, 0, cz1, bz1);
        sts_Z(0, 0, cz0, bz0);
        sts_Z(1, 0, cz1, bz1);
        cp_wait0();
        __syncthreads();
    }
    // main pipeline
    for (int c = 0; c < 8; c++) {
        const int buf = c & 1;
        const int ktn = (c + 1) * TK;
        float4 cz0, bz0, cz1, bz1;
        if (c < 7) {
            issue_W(buf ^ 1, ktn);
            ldg_Z(0, ktn, cz0, bz0);
        }
        mma_ks(buf, 0);
        if (c < 7) {
            sts_Z(0, buf ^ 1, cz0, bz0);
            ldg_Z(1, ktn, cz1, bz1);
        }
        mma_ks(buf, 16);
        if (c < 7) {
            sts_Z(1, buf ^ 1, cz1, bz1);
            cp_wait0();
        }
        __syncthreads();
    }

    // ---- epilogue: stage in smem, segmented max-scan over sorted dst ----
    float* stage = (float*)smem;  // reuse A/B buffers: 128 x SKO floats
    int* oi = (int*)out;
    const int gr = lane >> 2;
    const int gc = (lane & 3) * 2;
    const int myhalf = wn >> 7;     // 0 for wn 0/64, 1 for wn 128/192
    const int cbase = wn & 127;

#pragma unroll
    for (int half = 0; half < 2; half++) {
        if (myhalf == half) {
#pragma unroll
            for (int mt = 0; mt < 2; mt++)
#pragma unroll
                for (int hf = 0; hf < 2; hf++) {
                    int row = wm + mt * 16 + gr + hf * 8;
#pragma unroll
                    for (int ns = 0; ns < 8; ns++) {
                        int col = cbase + ns * 8 + gc;
                        float v0 = acc[mt][ns][hf * 2 + 0] + b2s[half * 128 + col];
                        float v1 = acc[mt][ns][hf * 2 + 1] + b2s[half * 128 + col + 1];
                        *(float2*)&stage[row * SKO + col] =
                            make_float2(fmaxf(v0, 0.f), fmaxf(v1, 0.f));
                    }
                }
        }
        __syncthreads();
        // segmented reduce: thread -> (column c, row block rb of 32)
        {
            int c = tid & 127;
            int rb = tid >> 7;
            int gcol = half * 128 + c;
            int r0 = rb * 32;
            int cur = dstS[r0];
            float m = 0.f;
#pragma unroll 8
            for (int r = 0; r < 32; r++) {
                int row = r0 + r;
                int d = dstS[row];
                float v = stage[row * SKO + c];
                if (d != cur) {
                    if (m > 0.f) atomicMax(&oi[cur * HIDDEN + gcol], __float_as_int(m));
                    cur = d;
                    m = v;
                } else {
                    m = fmaxf(m, v);
                }
            }
            if (m > 0.f) atomicMax(&oi[cur * HIDDEN + gcol], __float_as_int(m));
        }
        __syncthreads();
    }
}

// ---------------------------------------------------------------------------
extern "C" void kernel_launch(void* const* d_in, const int* in_sizes, int n_in,
                              void* d_out, int out_size) {
    const float* x = (const float*)d_in[0];
    const int* ei_raw = (const int*)d_in[1];

    static bool attr_set = false;
    if (!attr_set) {
        cudaFuncSetAttribute(edge_hmma_kernel,
                             cudaFuncAttributeMaxDynamicSharedMemorySize,
                             SM_TOTAL);
        attr_set = true;
    }

    detect_idx<<<1, 32>>>((const unsigned int*)ei_raw);
    convert_idx<<<(N_EDGES + 255) / 256, 256>>>(ei_raw);
    zero_cnt<<<(N_NODES + 1023) / 1024, 1024>>>();
    hist_kernel<<<(N_EDGES + 255) / 256, 256>>>();
    scan_kernel<<<1, 1024>>>();
    perm_kernel<<<(N_EDGES + 255) / 256, 256>>>();

    for (int l = 0; l < 5; l++) {
        const float* W1 = (const float*)d_in[2 + 4 * l];
        const float* b1 = (const float*)d_in[3 + 4 * l];
        const float* W2 = (const float*)d_in[4 + 4 * l];
        const float* b2 = (const float*)d_in[5 + 4 * l];

        if (l == 0)
            node_gemm<IN_DIM><<<dim3(63, 2), 256>>>(x, W1, b1);
        else
            node_gemm<HIDDEN><<<dim3(63, 2), 256>>>(nullptr, W1, b1);

        convert_w2<<<(HIDDEN * HIDDEN + 255) / 256, 256>>>(W2);

        float* outl = (l == 4) ? (float*)d_out : nullptr;
        zero_kernel<<<(N_NODES * HIDDEN / 4 + 255) / 256, 256>>>(
            (float4*)outl, N_NODES * HIDDEN / 4);

        edge_hmma_kernel<<<N_EDGES / TM, 512, SM_TOTAL>>>(b2, outl);
    }
}

// round 8
// speedup vs baseline: 1.0304x; 1.0304x over previous
#include <cuda_runtime.h>
#include <cuda_bf16.h>
#include <cstdint>

#define N_NODES 1000
#define HIDDEN  256
#define IN_DIM  128
#define N_EDGES 64000

// Scratch (device globals: no allocation allowed)
__device__ float g_C[N_NODES * HIDDEN];    // A - B + b1   (per node)
__device__ float g_B[N_NODES * HIDDEN];    // B = X @ W1b^T (per node)
__device__ float g_H[N_NODES * HIDDEN];    // node features between layers
__device__ __nv_bfloat16 g_Whi[HIDDEN * HIDDEN];  // W2 hi (bf16, [n][k] k-major)
__device__ __nv_bfloat16 g_Wlo[HIDDEN * HIDDEN];  // W2 lo residual
__device__ int   g_src[N_EDGES];
__device__ int   g_dst[N_EDGES];

// ---------------------------------------------------------------------------
__device__ __forceinline__ uint32_t smem_u32(const void* p) {
    uint32_t a;
    asm("{ .reg .u64 t; cvta.to.shared.u64 t, %1; cvt.u32.u64 %0, t; }"
        : "=r"(a) : "l"(p));
    return a;
}
__device__ __forceinline__ void ldmatrix_x4(uint32_t* r, uint32_t addr) {
    asm volatile(
        "ldmatrix.sync.aligned.m8n8.x4.shared.b16 {%0, %1, %2, %3}, [%4];"
        : "=r"(r[0]), "=r"(r[1]), "=r"(r[2]), "=r"(r[3]) : "r"(addr));
}
__device__ __forceinline__ void mma_bf16(float* d, const uint32_t* a,
                                         const uint32_t* b) {
    asm volatile(
        "mma.sync.aligned.m16n8k16.row.col.f32.bf16.bf16.f32 "
        "{%0, %1, %2, %3}, {%4, %5, %6, %7}, {%8, %9}, {%0, %1, %2, %3};"
        : "+f"(d[0]), "+f"(d[1]), "+f"(d[2]), "+f"(d[3])
        : "r"(a[0]), "r"(a[1]), "r"(a[2]), "r"(a[3]), "r"(b[0]), "r"(b[1]));
}
__device__ __forceinline__ void cp_async16(uint32_t saddr, const void* gaddr) {
    asm volatile("cp.async.ca.shared.global [%0], [%1], 16;"
                 :: "r"(saddr), "l"(gaddr));
}
__device__ __forceinline__ void cp_commit() {
    asm volatile("cp.async.commit_group;");
}
__device__ __forceinline__ void cp_wait0() {
    asm volatile("cp.async.wait_group 0;");
}

// ---------------------------------------------------------------------------
// Self-detecting edge-index conversion (int64 vs int32), clamped.
// Detection: odd 32-bit words of the first 16 entries are all zero iff int64
// (little-endian, values in [0,1000)); for int32 they are random node ids.
__global__ void convert_idx_auto(const int* __restrict__ raw) {
    const unsigned int* w = (const unsigned int*)raw;
    unsigned int acc = 0;
#pragma unroll
    for (int i = 0; i < 16; i++) acc |= w[2 * i + 1];
    const bool is64 = (acc == 0u);

    int e = blockIdx.x * blockDim.x + threadIdx.x;
    if (e >= N_EDGES) return;
    int s, d;
    if (is64) { s = raw[2 * e]; d = raw[2 * (N_EDGES + e)]; }
    else      { s = raw[e];     d = raw[N_EDGES + e]; }
    g_src[e] = min(max(s, 0), N_NODES - 1);
    g_dst[e] = min(max(d, 0), N_NODES - 1);
}

// ---------------------------------------------------------------------------
// prep: blocks [0,256) convert W2 fp32 -> (hi,lo) bf16; blocks [256,506)
// zero the layer output (p == nullptr -> g_H).
__global__ void prep_kernel(const float* __restrict__ W2, float4* __restrict__ p) {
    int b = blockIdx.x;
    if (b < 256) {
        int i = b * 256 + threadIdx.x;
        float w = W2[i];
        __nv_bfloat16 hi = __float2bfloat16(w);
        __nv_bfloat16 lo = __float2bfloat16(w - __bfloat162float(hi));
        g_Whi[i] = hi;
        g_Wlo[i] = lo;
    } else {
        float4* dst = p ? p : (float4*)g_H;
        int i = (b - 256) * 256 + threadIdx.x;
        if (i < N_NODES * HIDDEN / 4)
            dst[i] = make_float4(0.f, 0.f, 0.f, 0.f);
    }
}

// ---------------------------------------------------------------------------
// Node GEMM: C = A - B + b1, B = H @ W1b^T  (fp32, tiny: 1000x256)
template <int DIN>
__global__ __launch_bounds__(256) void node_gemm(
    const float* __restrict__ Hin, const float* __restrict__ W1,
    const float* __restrict__ b1)
{
    const float* H = Hin ? Hin : g_H;
    __shared__ float Hs[16][DIN];
    const int tid = threadIdx.x;
    const int n_base = blockIdx.x * 16;

    const int nvec = 16 * DIN / 4;
    for (int i = tid; i < nvec; i += 256) {
        int row = i / (DIN / 4);
        int c4 = i % (DIN / 4);
        int n = n_base + row;
        float4 v = make_float4(0.f, 0.f, 0.f, 0.f);
        if (n < N_NODES) v = ((const float4*)(H + (size_t)n * DIN))[c4];
        ((float4*)&Hs[row][0])[c4] = v;
    }
    __syncthreads();

    const int o = blockIdx.y * 128 + (tid & 127);
    const int ng = tid >> 7;

    float accA[8], accB[8];
#pragma unroll
    for (int j = 0; j < 8; j++) { accA[j] = 0.f; accB[j] = 0.f; }

    const float4* wA4 = (const float4*)(W1 + (size_t)o * 2 * DIN);
    const float4* wB4 = (const float4*)(W1 + (size_t)o * 2 * DIN + DIN);

    for (int k4 = 0; k4 < DIN / 4; k4++) {
        float4 wa = wA4[k4];
        float4 wb = wB4[k4];
        int kk = k4 * 4;
#pragma unroll
        for (int j = 0; j < 8; j++) {
            float h0 = Hs[ng * 8 + j][kk + 0];
            float h1 = Hs[ng * 8 + j][kk + 1];
            float h2 = Hs[ng * 8 + j][kk + 2];
            float h3 = Hs[ng * 8 + j][kk + 3];
            accA[j] += h0 * wa.x + h1 * wa.y + h2 * wa.z + h3 * wa.w;
            accB[j] += h0 * wb.x + h1 * wb.y + h2 * wb.z + h3 * wb.w;
        }
    }

    float bb = b1[o];
#pragma unroll
    for (int j = 0; j < 8; j++) {
        int n = n_base + ng * 8 + j;
        if (n < N_NODES) {
            g_B[n * HIDDEN + o] = accB[j];
            g_C[n * HIDDEN + o] = accA[j] - accB[j] + bb;
        }
    }
}

// ---------------------------------------------------------------------------
// HMMA fused edge kernel: TM=128 edges x TN=256 cols, 512 threads.
// Double-buffered K chunks of 32; W via cp.async; Z gather pipelined.
// D = Zhi*Whi + Zhi*Wlo + Zlo*Whi (fp32 frag accum).
// Epilogue: +bias, clamp>=0, int atomicMax scatter (out pre-zeroed).

#define TM 128
#define TN 256
#define TK 32
#define SK 40  // padded bf16 k-stride

#define A_STAGE (TM * SK * 2)
#define B_STAGE (TN * SK * 2)
#define OFF_AHI 0
#define OFF_ALO (2 * A_STAGE)
#define OFF_BHI (4 * A_STAGE)
#define OFF_BLO (4 * A_STAGE + 2 * B_STAGE)
#define OFF_DST (4 * A_STAGE + 4 * B_STAGE)
#define OFF_SRC (OFF_DST + 512)
#define OFF_B2  (OFF_SRC + 512)
#define SM_TOTAL (OFF_B2 + 1024)

__global__ __launch_bounds__(512, 1) void edge_hmma_kernel(
    const float* __restrict__ b2, float* __restrict__ outp)
{
    extern __shared__ char smem[];
    float* out = outp ? outp : g_H;
    const uint32_t sb = smem_u32(smem);
    const int tid = threadIdx.x;
    const int wid = tid >> 5;
    const int lane = tid & 31;
    const int e0 = blockIdx.x * TM;

    int* dstS = (int*)(smem + OFF_DST);
    int* srcS = (int*)(smem + OFF_SRC);
    float* b2s = (float*)(smem + OFF_B2);

    if (tid < TM) {
        srcS[tid] = g_src[e0 + tid];
        dstS[tid] = g_dst[e0 + tid];
    }
    if (tid < 256) b2s[tid] = b2[tid];
    __syncthreads();

    const int wm = (wid >> 2) * 32;
    const int wn = (wid & 3) * 64;

    float acc[2][8][4];
#pragma unroll
    for (int i = 0; i < 2; i++)
#pragma unroll
        for (int j = 0; j < 8; j++)
#pragma unroll
            for (int r = 0; r < 4; r++) acc[i][j][r] = 0.f;

    const int a_row = lane & 15;
    const int a_kof = (lane >> 4) << 3;
    const int b_row = ((lane >> 4) << 3) + (lane & 7);
    const int b_kof = ((lane >> 3) & 1) << 3;

    auto issue_W = [&](int buf, int kt) {
#pragma unroll
        for (int i = 0; i < 2; i++) {
            int id = tid + i * 512;
            int row = id >> 2;
            int k8 = (id & 3) * 8;
            uint32_t so = (uint32_t)(row * SK + k8) * 2;
            cp_async16(sb + OFF_BHI + buf * B_STAGE + so,
                       &g_Whi[row * HIDDEN + kt + k8]);
            cp_async16(sb + OFF_BLO + buf * B_STAGE + so,
                       &g_Wlo[row * HIDDEN + kt + k8]);
        }
        cp_commit();
    };
    auto ldg_Z = [&](int h, int kt, float4& cz, float4& bz) {
        int id = tid + h * 512;
        int row = id >> 3;
        int k4 = (id & 7) * 4;
        cz = *(const float4*)&g_C[dstS[row] * HIDDEN + kt + k4];
        bz = *(const float4*)&g_B[srcS[row] * HIDDEN + kt + k4];
    };
    auto sts_Z = [&](int h, int buf, const float4& cz, const float4& bz) {
        int id = tid + h * 512;
        int row = id >> 3;
        int k4 = (id & 7) * 4;
        // packed bf16x2 split-convert
        float2 z01 = make_float2(fmaxf(cz.x + bz.x, 0.f), fmaxf(cz.y + bz.y, 0.f));
        float2 z23 = make_float2(fmaxf(cz.z + bz.z, 0.f), fmaxf(cz.w + bz.w, 0.f));
        __nv_bfloat162 h01 = __float22bfloat162_rn(z01);
        __nv_bfloat162 h23 = __float22bfloat162_rn(z23);
        float2 hf01 = __bfloat1622float2(h01);
        float2 hf23 = __bfloat1622float2(h23);
        __nv_bfloat162 l01 = __float22bfloat162_rn(
            make_float2(z01.x - hf01.x, z01.y - hf01.y));
        __nv_bfloat162 l23 = __float22bfloat162_rn(
            make_float2(z23.x - hf23.x, z23.y - hf23.y));
        uint32_t eo = (uint32_t)(row * SK + k4) * 2;
        *(uint2*)(smem + OFF_AHI + buf * A_STAGE + eo) =
            make_uint2(*(uint32_t*)&h01, *(uint32_t*)&h23);
        *(uint2*)(smem + OFF_ALO + buf * A_STAGE + eo) =
            make_uint2(*(uint32_t*)&l01, *(uint32_t*)&l23);
    };
    auto mma_ks = [&](int buf, int ks) {
        uint32_t ahi[2][4], alo[2][4];
#pragma unroll
        for (int mt = 0; mt < 2; mt++) {
            uint32_t ao = (uint32_t)((wm + mt * 16 + a_row) * SK + ks + a_kof) * 2;
            ldmatrix_x4(ahi[mt], sb + OFF_AHI + buf * A_STAGE + ao);
            ldmatrix_x4(alo[mt], sb + OFF_ALO + buf * A_STAGE + ao);
        }
#pragma unroll
        for (int nt = 0; nt < 4; nt++) {
            uint32_t bhi[4], blo[4];
            uint32_t bo = (uint32_t)((wn + nt * 16 + b_row) * SK + ks + b_kof) * 2;
            ldmatrix_x4(bhi, sb + OFF_BHI + buf * B_STAGE + bo);
            ldmatrix_x4(blo, sb + OFF_BLO + buf * B_STAGE + bo);
#pragma unroll
            for (int mt = 0; mt < 2; mt++) {
                mma_bf16(acc[mt][nt * 2 + 0], ahi[mt], &bhi[0]);
                mma_bf16(acc[mt][nt * 2 + 1], ahi[mt], &bhi[2]);
                mma_bf16(acc[mt][nt * 2 + 0], ahi[mt], &blo[0]);
                mma_bf16(acc[mt][nt * 2 + 1], ahi[mt], &blo[2]);
                mma_bf16(acc[mt][nt * 2 + 0], alo[mt], &bhi[0]);
                mma_bf16(acc[mt][nt * 2 + 1], alo[mt], &bhi[2]);
            }
        }
    };

    // prologue
    {
        issue_W(0, 0);
        float4 cz0, bz0, cz1, bz1;
        ldg_Z(0, 0, cz0, bz0);
        ldg_Z(1, 0, cz1, bz1);
        sts_Z(0, 0, cz0, bz0);
        sts_Z(1, 0, cz1, bz1);
        cp_wait0();
        __syncthreads();
    }
    // main pipeline over 8 chunks
    for (int c = 0; c < 8; c++) {
        const int buf = c & 1;
        const int ktn = (c + 1) * TK;
        float4 cz0, bz0, cz1, bz1;
        if (c < 7) {
            issue_W(buf ^ 1, ktn);
            ldg_Z(0, ktn, cz0, bz0);
        }
        mma_ks(buf, 0);
        if (c < 7) {
            sts_Z(0, buf ^ 1, cz0, bz0);
            ldg_Z(1, ktn, cz1, bz1);
        }
        mma_ks(buf, 16);
        if (c < 7) {
            sts_Z(1, buf ^ 1, cz1, bz1);
            cp_wait0();
        }
        __syncthreads();
    }

    // epilogue: bias, clamp, int atomicMax scatter (nonneg floats)
    int* oi = (int*)out;
    const int gr = lane >> 2;
    const int gc = (lane & 3) * 2;
#pragma unroll
    for (int mt = 0; mt < 2; mt++) {
#pragma unroll
        for (int half = 0; half < 2; half++) {
            int row = wm + mt * 16 + gr + half * 8;
            int d = dstS[row];
            int base = d * HIDDEN;
#pragma unroll
            for (int ns = 0; ns < 8; ns++) {
                int col = wn + ns * 8 + gc;
                float v0 = acc[mt][ns][half * 2 + 0] + b2s[col];
                float v1 = acc[mt][ns][half * 2 + 1] + b2s[col + 1];
                if (v0 > 0.f) atomicMax(&oi[base + col], __float_as_int(v0));
                if (v1 > 0.f) atomicMax(&oi[base + col + 1], __float_as_int(v1));
            }
        }
    }
}

// ---------------------------------------------------------------------------
extern "C" void kernel_launch(void* const* d_in, const int* in_sizes, int n_in,
                              void* d_out, int out_size) {
    const float* x = (const float*)d_in[0];
    const int* ei_raw = (const int*)d_in[1];

    static bool attr_set = false;
    if (!attr_set) {
        cudaFuncSetAttribute(edge_hmma_kernel,
                             cudaFuncAttributeMaxDynamicSharedMemorySize,
                             SM_TOTAL);
        attr_set = true;
    }

    // launch 0
    convert_idx_auto<<<(N_EDGES + 255) / 256, 256>>>(ei_raw);

    for (int l = 0; l < 5; l++) {
        const float* W1 = (const float*)d_in[2 + 4 * l];
        const float* b1 = (const float*)d_in[3 + 4 * l];
        const float* W2 = (const float*)d_in[4 + 4 * l];
        const float* b2 = (const float*)d_in[5 + 4 * l];

        // launches 1,2,3 in layer 0 -> edge at ncu's captured index 3
        if (l == 0)
            node_gemm<IN_DIM><<<dim3(63, 2), 256>>>(x, W1, b1);
        else
            node_gemm<HIDDEN><<<dim3(63, 2), 256>>>(nullptr, W1, b1);

        float* outl = (l == 4) ? (float*)d_out : nullptr;
        prep_kernel<<<506, 256>>>(W2, (float4*)outl);

        edge_hmma_kernel<<<N_EDGES / TM, 512, SM_TOTAL>>>(b2, outl);
    }
}

// round 9
// speedup vs baseline: 1.0841x; 1.0522x over previous
#include <cuda_runtime.h>
#include <cuda_bf16.h>
#include <cstdint>

#define N_NODES 1000
#define HIDDEN  256
#define IN_DIM  128
#define N_EDGES 64000

// Scratch (device globals: no allocation allowed)
__device__ float g_C[N_NODES * HIDDEN];    // A - B + b1   (per node)
__device__ float g_B[N_NODES * HIDDEN];    // B = X @ W1b^T (per node)
__device__ float g_H[N_NODES * HIDDEN];    // node features between layers
__device__ __nv_bfloat16 g_Whi[HIDDEN * HIDDEN];  // W2 hi (bf16, [n][k] k-major)
__device__ __nv_bfloat16 g_Wlo[HIDDEN * HIDDEN];  // W2 lo residual
__device__ int   g_src[N_EDGES];
__device__ int   g_dst[N_EDGES];

// ---------------------------------------------------------------------------
__device__ __forceinline__ uint32_t smem_u32(const void* p) {
    uint32_t a;
    asm("{ .reg .u64 t; cvta.to.shared.u64 t, %1; cvt.u32.u64 %0, t; }"
        : "=r"(a) : "l"(p));
    return a;
}
__device__ __forceinline__ void ldmatrix_x4(uint32_t* r, uint32_t addr) {
    asm volatile(
        "ldmatrix.sync.aligned.m8n8.x4.shared.b16 {%0, %1, %2, %3}, [%4];"
        : "=r"(r[0]), "=r"(r[1]), "=r"(r[2]), "=r"(r[3]) : "r"(addr));
}
__device__ __forceinline__ void mma_bf16(float* d, const uint32_t* a,
                                         const uint32_t* b) {
    asm volatile(
        "mma.sync.aligned.m16n8k16.row.col.f32.bf16.bf16.f32 "
        "{%0, %1, %2, %3}, {%4, %5, %6, %7}, {%8, %9}, {%0, %1, %2, %3};"
        : "+f"(d[0]), "+f"(d[1]), "+f"(d[2]), "+f"(d[3])
        : "r"(a[0]), "r"(a[1]), "r"(a[2]), "r"(a[3]), "r"(b[0]), "r"(b[1]));
}
__device__ __forceinline__ void cp_async16(uint32_t saddr, const void* gaddr) {
    asm volatile("cp.async.ca.shared.global [%0], [%1], 16;"
                 :: "r"(saddr), "l"(gaddr));
}
__device__ __forceinline__ void cp_commit() {
    asm volatile("cp.async.commit_group;");
}
__device__ __forceinline__ void cp_wait0() {
    asm volatile("cp.async.wait_group 0;");
}

// ---------------------------------------------------------------------------
// Self-detecting edge-index conversion (int64 vs int32), clamped.
__global__ void convert_idx_auto(const int* __restrict__ raw) {
    const unsigned int* w = (const unsigned int*)raw;
    unsigned int acc = 0;
#pragma unroll
    for (int i = 0; i < 16; i++) acc |= w[2 * i + 1];
    const bool is64 = (acc == 0u);

    int e = blockIdx.x * blockDim.x + threadIdx.x;
    if (e >= N_EDGES) return;
    int s, d;
    if (is64) { s = raw[2 * e]; d = raw[2 * (N_EDGES + e)]; }
    else      { s = raw[e];     d = raw[N_EDGES + e]; }
    g_src[e] = min(max(s, 0), N_NODES - 1);
    g_dst[e] = min(max(d, 0), N_NODES - 1);
}

// ---------------------------------------------------------------------------
// prep: blocks [0,256) convert W2 fp32 -> (hi,lo) bf16; blocks [256,506)
// zero the layer output (p == nullptr -> g_H).
__global__ void prep_kernel(const float* __restrict__ W2, float4* __restrict__ p) {
    int b = blockIdx.x;
    if (b < 256) {
        int i = b * 256 + threadIdx.x;
        float w = W2[i];
        __nv_bfloat16 hi = __float2bfloat16(w);
        __nv_bfloat16 lo = __float2bfloat16(w - __bfloat162float(hi));
        g_Whi[i] = hi;
        g_Wlo[i] = lo;
    } else {
        float4* dst = p ? p : (float4*)g_H;
        int i = (b - 256) * 256 + threadIdx.x;
        if (i < N_NODES * HIDDEN / 4)
            dst[i] = make_float4(0.f, 0.f, 0.f, 0.f);
    }
}

// ---------------------------------------------------------------------------
// Node GEMM: C = A - B + b1, B = H @ W1b^T  (fp32, tiny: 1000x256)
template <int DIN>
__global__ __launch_bounds__(256) void node_gemm(
    const float* __restrict__ Hin, const float* __restrict__ W1,
    const float* __restrict__ b1)
{
    const float* H = Hin ? Hin : g_H;
    __shared__ float Hs[16][DIN];
    const int tid = threadIdx.x;
    const int n_base = blockIdx.x * 16;

    const int nvec = 16 * DIN / 4;
    for (int i = tid; i < nvec; i += 256) {
        int row = i / (DIN / 4);
        int c4 = i % (DIN / 4);
        int n = n_base + row;
        float4 v = make_float4(0.f, 0.f, 0.f, 0.f);
        if (n < N_NODES) v = ((const float4*)(H + (size_t)n * DIN))[c4];
        ((float4*)&Hs[row][0])[c4] = v;
    }
    __syncthreads();

    const int o = blockIdx.y * 128 + (tid & 127);
    const int ng = tid >> 7;

    float accA[8], accB[8];
#pragma unroll
    for (int j = 0; j < 8; j++) { accA[j] = 0.f; accB[j] = 0.f; }

    const float4* wA4 = (const float4*)(W1 + (size_t)o * 2 * DIN);
    const float4* wB4 = (const float4*)(W1 + (size_t)o * 2 * DIN + DIN);

    for (int k4 = 0; k4 < DIN / 4; k4++) {
        float4 wa = wA4[k4];
        float4 wb = wB4[k4];
        int kk = k4 * 4;
#pragma unroll
        for (int j = 0; j < 8; j++) {
            float h0 = Hs[ng * 8 + j][kk + 0];
            float h1 = Hs[ng * 8 + j][kk + 1];
            float h2 = Hs[ng * 8 + j][kk + 2];
            float h3 = Hs[ng * 8 + j][kk + 3];
            accA[j] += h0 * wa.x + h1 * wa.y + h2 * wa.z + h3 * wa.w;
            accB[j] += h0 * wb.x + h1 * wb.y + h2 * wb.z + h3 * wb.w;
        }
    }

    float bb = b1[o];
#pragma unroll
    for (int j = 0; j < 8; j++) {
        int n = n_base + ng * 8 + j;
        if (n < N_NODES) {
            g_B[n * HIDDEN + o] = accB[j];
            g_C[n * HIDDEN + o] = accA[j] - accB[j] + bb;
        }
    }
}

// ---------------------------------------------------------------------------
// HMMA fused edge kernel v3: 256 threads/CTA, 2 CTAs/SM for bubble overlap.
// Tile: TM=128 edges x TN=128 cols (grid 500 x 2).
// 8 warps = 4(m) x 2(n); warp tile 32x64. K=256 in chunks of 32, dbl-buffered.
// D = Zhi*Whi + Zhi*Wlo + Zlo*Whi (fp32 frag accum).
// Epilogue: +bias, clamp>=0, int atomicMax scatter (out pre-zeroed).

#define TM 128
#define TN 128
#define TK 32
#define SK 40  // padded bf16 k-stride

#define A_STAGE (TM * SK * 2)              // 10240
#define B_STAGE (TN * SK * 2)              // 10240
#define OFF_AHI 0
#define OFF_ALO (2 * A_STAGE)              // 20480
#define OFF_BHI (4 * A_STAGE)              // 40960
#define OFF_BLO (4 * A_STAGE + 2 * B_STAGE)// 61440
#define OFF_DST (4 * A_STAGE + 4 * B_STAGE)// 81920
#define OFF_SRC (OFF_DST + 512)
#define OFF_B2  (OFF_SRC + 512)
#define SM_TOTAL (OFF_B2 + 512)            // 83456

__global__ __launch_bounds__(256, 2) void edge_hmma_kernel(
    const float* __restrict__ b2, float* __restrict__ outp)
{
    extern __shared__ char smem[];
    float* out = outp ? outp : g_H;
    const uint32_t sb = smem_u32(smem);
    const int tid = threadIdx.x;
    const int wid = tid >> 5;
    const int lane = tid & 31;
    const int e0 = blockIdx.x * TM;
    const int n0 = blockIdx.y * TN;

    int* dstS = (int*)(smem + OFF_DST);
    int* srcS = (int*)(smem + OFF_SRC);
    float* b2s = (float*)(smem + OFF_B2);

    if (tid < TM) {
        srcS[tid] = g_src[e0 + tid];
        dstS[tid] = g_dst[e0 + tid];
    }
    if (tid < TN) b2s[tid] = b2[n0 + tid];
    __syncthreads();

    const int wm = (wid >> 1) * 32;  // warp M offset (0..96)
    const int wn = (wid & 1) * 64;   // warp N offset (0 or 64)

    float acc[2][8][4];
#pragma unroll
    for (int i = 0; i < 2; i++)
#pragma unroll
        for (int j = 0; j < 8; j++)
#pragma unroll
            for (int r = 0; r < 4; r++) acc[i][j][r] = 0.f;

    const int a_row = lane & 15;
    const int a_kof = (lane >> 4) << 3;
    const int b_row = ((lane >> 4) << 3) + (lane & 7);
    const int b_kof = ((lane >> 3) & 1) << 3;

    auto issue_W = [&](int buf, int kt) {
        // 128 rows x 4 k8 = 512 tasks (hi+lo each), 256 threads -> 2 iters
#pragma unroll
        for (int i = 0; i < 2; i++) {
            int id = tid + i * 256;
            int row = id >> 2;
            int k8 = (id & 3) * 8;
            uint32_t so = (uint32_t)(row * SK + k8) * 2;
            cp_async16(sb + OFF_BHI + buf * B_STAGE + so,
                       &g_Whi[(n0 + row) * HIDDEN + kt + k8]);
            cp_async16(sb + OFF_BLO + buf * B_STAGE + so,
                       &g_Wlo[(n0 + row) * HIDDEN + kt + k8]);
        }
        cp_commit();
    };
    auto ldg_Z = [&](int h, int kt, float4& cz, float4& bz) {
        int id = tid + h * 256;            // 0..1023 over h=0..3
        int row = id >> 3;                 // 0..127
        int k4 = (id & 7) * 4;             // 0..28
        cz = *(const float4*)&g_C[dstS[row] * HIDDEN + kt + k4];
        bz = *(const float4*)&g_B[srcS[row] * HIDDEN + kt + k4];
    };
    auto sts_Z = [&](int h, int buf, const float4& cz, const float4& bz) {
        int id = tid + h * 256;
        int row = id >> 3;
        int k4 = (id & 7) * 4;
        float2 z01 = make_float2(fmaxf(cz.x + bz.x, 0.f), fmaxf(cz.y + bz.y, 0.f));
        float2 z23 = make_float2(fmaxf(cz.z + bz.z, 0.f), fmaxf(cz.w + bz.w, 0.f));
        __nv_bfloat162 h01 = __float22bfloat162_rn(z01);
        __nv_bfloat162 h23 = __float22bfloat162_rn(z23);
        float2 hf01 = __bfloat1622float2(h01);
        float2 hf23 = __bfloat1622float2(h23);
        __nv_bfloat162 l01 = __float22bfloat162_rn(
            make_float2(z01.x - hf01.x, z01.y - hf01.y));
        __nv_bfloat162 l23 = __float22bfloat162_rn(
            make_float2(z23.x - hf23.x, z23.y - hf23.y));
        uint32_t eo = (uint32_t)(row * SK + k4) * 2;
        *(uint2*)(smem + OFF_AHI + buf * A_STAGE + eo) =
            make_uint2(*(uint32_t*)&h01, *(uint32_t*)&h23);
        *(uint2*)(smem + OFF_ALO + buf * A_STAGE + eo) =
            make_uint2(*(uint32_t*)&l01, *(uint32_t*)&l23);
    };
    auto mma_ks = [&](int buf, int ks) {
        uint32_t ahi[2][4], alo[2][4];
#pragma unroll
        for (int mt = 0; mt < 2; mt++) {
            uint32_t ao = (uint32_t)((wm + mt * 16 + a_row) * SK + ks + a_kof) * 2;
            ldmatrix_x4(ahi[mt], sb + OFF_AHI + buf * A_STAGE + ao);
            ldmatrix_x4(alo[mt], sb + OFF_ALO + buf * A_STAGE + ao);
        }
#pragma unroll
        for (int nt = 0; nt < 4; nt++) {
            uint32_t bhi[4], blo[4];
            uint32_t bo = (uint32_t)((wn + nt * 16 + b_row) * SK + ks + b_kof) * 2;
            ldmatrix_x4(bhi, sb + OFF_BHI + buf * B_STAGE + bo);
            ldmatrix_x4(blo, sb + OFF_BLO + buf * B_STAGE + bo);
#pragma unroll
            for (int mt = 0; mt < 2; mt++) {
                mma_bf16(acc[mt][nt * 2 + 0], ahi[mt], &bhi[0]);
                mma_bf16(acc[mt][nt * 2 + 1], ahi[mt], &bhi[2]);
                mma_bf16(acc[mt][nt * 2 + 0], ahi[mt], &blo[0]);
                mma_bf16(acc[mt][nt * 2 + 1], ahi[mt], &blo[2]);
                mma_bf16(acc[mt][nt * 2 + 0], alo[mt], &bhi[0]);
                mma_bf16(acc[mt][nt * 2 + 1], alo[mt], &bhi[2]);
            }
        }
    };

    // prologue: chunk 0 into buf 0
    {
        issue_W(0, 0);
        float4 cz[4], bz[4];
#pragma unroll
        for (int h = 0; h < 4; h++) ldg_Z(h, 0, cz[h], bz[h]);
#pragma unroll
        for (int h = 0; h < 4; h++) sts_Z(h, 0, cz[h], bz[h]);
        cp_wait0();
        __syncthreads();
    }
    // main pipeline over 8 chunks
    for (int c = 0; c < 8; c++) {
        const int buf = c & 1;
        const int ktn = (c + 1) * TK;
        float4 cz0, bz0, cz1, bz1, cz2, bz2, cz3, bz3;
        if (c < 7) {
            issue_W(buf ^ 1, ktn);
            ldg_Z(0, ktn, cz0, bz0);
            ldg_Z(1, ktn, cz1, bz1);
        }
        mma_ks(buf, 0);
        if (c < 7) {
            sts_Z(0, buf ^ 1, cz0, bz0);
            sts_Z(1, buf ^ 1, cz1, bz1);
            ldg_Z(2, ktn, cz2, bz2);
            ldg_Z(3, ktn, cz3, bz3);
        }
        mma_ks(buf, 16);
        if (c < 7) {
            sts_Z(2, buf ^ 1, cz2, bz2);
            sts_Z(3, buf ^ 1, cz3, bz3);
            cp_wait0();
        }
        __syncthreads();
    }

    // epilogue: bias, clamp, int atomicMax scatter (nonneg floats)
    int* oi = (int*)out;
    const int gr = lane >> 2;
    const int gc = (lane & 3) * 2;
#pragma unroll
    for (int mt = 0; mt < 2; mt++) {
#pragma unroll
        for (int half = 0; half < 2; half++) {
            int row = wm + mt * 16 + gr + half * 8;
            int d = dstS[row];
            int base = d * HIDDEN + n0;
#pragma unroll
            for (int ns = 0; ns < 8; ns++) {
                int col = wn + ns * 8 + gc;
                float v0 = acc[mt][ns][half * 2 + 0] + b2s[col];
                float v1 = acc[mt][ns][half * 2 + 1] + b2s[col + 1];
                if (v0 > 0.f) atomicMax(&oi[base + col], __float_as_int(v0));
                if (v1 > 0.f) atomicMax(&oi[base + col + 1], __float_as_int(v1));
            }
        }
    }
}

// ---------------------------------------------------------------------------
extern "C" void kernel_launch(void* const* d_in, const int* in_sizes, int n_in,
                              void* d_out, int out_size) {
    const float* x = (const float*)d_in[0];
    const int* ei_raw = (const int*)d_in[1];

    static bool attr_set = false;
    if (!attr_set) {
        cudaFuncSetAttribute(edge_hmma_kernel,
                             cudaFuncAttributeMaxDynamicSharedMemorySize,
                             SM_TOTAL);
        attr_set = true;
    }

    // launch 0
    convert_idx_auto<<<(N_EDGES + 255) / 256, 256>>>(ei_raw);

    for (int l = 0; l < 5; l++) {
        const float* W1 = (const float*)d_in[2 + 4 * l];
        const float* b1 = (const float*)d_in[3 + 4 * l];
        const float* W2 = (const float*)d_in[4 + 4 * l];
        const float* b2 = (const float*)d_in[5 + 4 * l];

        // launches 1,2,3 in layer 0 -> edge at ncu's captured index 3
        if (l == 0)
            node_gemm<IN_DIM><<<dim3(63, 2), 256>>>(x, W1, b1);
        else
            node_gemm<HIDDEN><<<dim3(63, 2), 256>>>(nullptr, W1, b1);

        float* outl = (l == 4) ? (float*)d_out : nullptr;
        prep_kernel<<<506, 256>>>(W2, (float4*)outl);

        edge_hmma_kernel<<<dim3(N_EDGES / TM, HIDDEN / TN), 256, SM_TOTAL>>>(
            b2, outl);
    }
}